// round 2
// baseline (speedup 1.0000x reference)
#include <cuda_runtime.h>
#include <math.h>

#define KK 64
#define PP 256
#define RR 16
#define NT 32          // rows of X per block (main kernel)
#define PC 8           // p-chunk size
#define KSTR 20        // padded smem stride (floats) per k for conflict-free LDS.128

// Scratch (device globals: no allocation allowed)
__device__ float  g_A[PP * KK * RR];   // [p][k][r]  = M L^{-T}, 1 MB
__device__ float  g_c[KK];             // log_softmax(pi)_k - 0.5*logdet_k
__device__ float  g_logdet[KK];
__device__ double g_acc;

// ---------------- prep1: per component k: D = I + M^T M, Cholesky, logdet, A = M L^{-T}
__global__ void prep1_kernel(const float* __restrict__ M) {
    __shared__ float sM[PP * RR];       // 16 KB, M_k as [p][r]
    __shared__ float sD[RR][RR + 1];
    const int k = blockIdx.x;
    const int tid = threadIdx.x;        // 256 threads

    // load M_k (coalesced float4)
    const float4* Mg = (const float4*)(M + (size_t)k * PP * RR);
    float4* sM4 = (float4*)sM;
#pragma unroll
    for (int i = 0; i < 4; ++i) sM4[tid + i * 256] = Mg[tid + i * 256];
    __syncthreads();

    // D[r][s] = (r==s) + sum_p M[p][r] M[p][s]
    {
        int r = tid >> 4, s = tid & 15;
        float d = (r == s) ? 1.0f : 0.0f;
        for (int p = 0; p < PP; ++p) d += sM[p * RR + r] * sM[p * RR + s];
        sD[r][s] = d;
    }
    __syncthreads();

    // Cholesky (lower) in-place, by thread 0; logdet = 2*sum log L_ii
    if (tid == 0) {
        float logdet = 0.f;
        for (int j = 0; j < RR; ++j) {
            float sum = sD[j][j];
            for (int t = 0; t < j; ++t) sum -= sD[j][t] * sD[j][t];
            float Ljj = sqrtf(sum);
            sD[j][j] = Ljj;
            logdet += 2.0f * logf(Ljj);
            float inv = 1.0f / Ljj;
            for (int i = j + 1; i < RR; ++i) {
                float s2 = sD[i][j];
                for (int t = 0; t < j; ++t) s2 -= sD[i][t] * sD[j][t];
                sD[i][j] = s2 * inv;
            }
        }
        g_logdet[k] = logdet;
    }
    __syncthreads();

    // Forward solve L y = m_p for each row p of M_k; A[p][k][:] = y
    {
        const int p = tid;
        float y[RR];
#pragma unroll
        for (int i = 0; i < RR; ++i) {
            float s2 = sM[p * RR + i];
#pragma unroll
            for (int j = 0; j < RR; ++j)
                if (j < i) s2 -= sD[i][j] * y[j];
            y[i] = s2 / sD[i][i];
        }
        float* dst = g_A + ((size_t)p * KK + k) * RR;
#pragma unroll
        for (int i = 0; i < RR; ++i) dst[i] = y[i];
    }
}

// ---------------- prep2: c_k = log_softmax(pi)_k - 0.5*logdet_k ; zero accumulator
__global__ void prep2_kernel(const float* __restrict__ pi) {
    __shared__ float sp[KK];
    __shared__ float lse_s;
    const int t = threadIdx.x;          // 64 threads
    sp[t] = pi[t];
    __syncthreads();
    if (t == 0) {
        float m = sp[0];
        for (int i = 1; i < KK; ++i) m = fmaxf(m, sp[i]);
        float s = 0.f;
        for (int i = 0; i < KK; ++i) s += expf(sp[i] - m);
        lse_s = m + logf(s);
        g_acc = 0.0;
    }
    __syncthreads();
    g_c[t] = (sp[t] - lse_s) - 0.5f * g_logdet[t];
}

// ---------------- main: Y = X * A, quad = group sums of squares, fused logsumexp
__global__ void __launch_bounds__(512, 1)
main_kernel(const float* __restrict__ X, int N) {
    __shared__ __align__(16) float sA[PC][KK * KSTR];  // 40 KB
    __shared__ __align__(16) float sX[NT][PC];         // 1 KB
    __shared__ float plse[16];

    const int tid = threadIdx.x;
    const int k = tid & 63;
    const int g = tid >> 6;            // 0..7 -> 4 rows each
    const int n0 = blockIdx.x * NT;

    float y[4][RR];
#pragma unroll
    for (int i = 0; i < 4; ++i)
#pragma unroll
        for (int r = 0; r < RR; ++r) y[i][r] = 0.f;

    // prefetch registers (double-buffer global->reg->smem)
    float4 rA[4];
    float4 rX;
    {
        const float4* Ag = (const float4*)g_A;   // chunk 0 base
#pragma unroll
        for (int i = 0; i < 4; ++i) rA[i] = Ag[tid + i * 512];
        if (tid < 64) {
            int n = tid >> 1, h = tid & 1;
            int row = n0 + n; if (row > N - 1) row = N - 1;
            rX = *(const float4*)(X + (size_t)row * PP + h * 4);
        }
    }

    for (int pc = 0; pc < PP / PC; ++pc) {
        __syncthreads();                         // prev compute done reading smem
        // store prefetched chunk to smem (padded layout)
#pragma unroll
        for (int i = 0; i < 4; ++i) {
            int f = tid + i * 512;               // float4 idx within chunk
            int p = f >> 8;                      // 0..7
            int rem = f & 255;
            int k2 = rem >> 2;
            int j = rem & 3;
            *(float4*)&sA[p][k2 * KSTR + j * 4] = rA[i];
        }
        if (tid < 64) {
            int n = tid >> 1, h = tid & 1;
            *(float4*)&sX[n][h * 4] = rX;
        }
        __syncthreads();

        // prefetch next chunk (overlaps with compute below)
        if (pc + 1 < PP / PC) {
            const float4* Ag = (const float4*)g_A + (size_t)(pc + 1) * 2048;
#pragma unroll
            for (int i = 0; i < 4; ++i) rA[i] = Ag[tid + i * 512];
            if (tid < 64) {
                int n = tid >> 1, h = tid & 1;
                int row = n0 + n; if (row > N - 1) row = N - 1;
                rX = *(const float4*)(X + (size_t)row * PP + (pc + 1) * PC + h * 4);
            }
        }

        // compute: 512 FFMA per thread per chunk
        const int kk = k * KSTR;
        const int gn = g * 4;
#pragma unroll
        for (int p = 0; p < PC; ++p) {
            float4 a0 = *(const float4*)&sA[p][kk + 0];
            float4 a1 = *(const float4*)&sA[p][kk + 4];
            float4 a2 = *(const float4*)&sA[p][kk + 8];
            float4 a3 = *(const float4*)&sA[p][kk + 12];
            float xv0 = sX[gn + 0][p];
            float xv1 = sX[gn + 1][p];
            float xv2 = sX[gn + 2][p];
            float xv3 = sX[gn + 3][p];
            float av[16] = {a0.x, a0.y, a0.z, a0.w, a1.x, a1.y, a1.z, a1.w,
                            a2.x, a2.y, a2.z, a2.w, a3.x, a3.y, a3.z, a3.w};
#pragma unroll
            for (int r = 0; r < 16; ++r) {
                y[0][r] = fmaf(xv0, av[r], y[0][r]);
                y[1][r] = fmaf(xv1, av[r], y[1][r]);
                y[2][r] = fmaf(xv2, av[r], y[2][r]);
                y[3][r] = fmaf(xv3, av[r], y[3][r]);
            }
        }
    }

    // ---- epilogue: quad -> density term, then logsumexp over k per row n
    const float ck = g_c[k];
    __syncthreads();                              // everyone done reading sA
    float* vsm = &sA[0][0];                       // reuse: [NT][64]
#pragma unroll
    for (int i = 0; i < 4; ++i) {
        float q = 0.f;
#pragma unroll
        for (int r = 0; r < RR; ++r) q += y[i][r] * y[i][r];
        // density (minus the constant logSA): c_k - (p/2)*log(1 - quad)
        float v = ck - 128.0f * log1pf(-q);
        vsm[(g * 4 + i) * 64 + k] = v;
    }
    __syncthreads();

    // warp wid reduces rows n = 2*wid, 2*wid+1 over 64 components
    const int wid = tid >> 5, lane = tid & 31;
    float wsum = 0.f;
#pragma unroll
    for (int half = 0; half < 2; ++half) {
        int n = wid * 2 + half;
        float v1 = vsm[n * 64 + lane];
        float v2 = vsm[n * 64 + 32 + lane];
        float m = fmaxf(v1, v2);
#pragma unroll
        for (int o = 16; o > 0; o >>= 1) m = fmaxf(m, __shfl_xor_sync(0xffffffffu, m, o));
        float s = expf(v1 - m) + expf(v2 - m);
#pragma unroll
        for (int o = 16; o > 0; o >>= 1) s += __shfl_xor_sync(0xffffffffu, s, o);
        if (n0 + n < N) wsum += m + logf(s);
    }
    if (lane == 0) plse[wid] = wsum;
    __syncthreads();
    if (tid == 0) {
        float bs = 0.f;
#pragma unroll
        for (int i = 0; i < 16; ++i) bs += plse[i];
        atomicAdd(&g_acc, (double)bs);
    }
}

// ---------------- finish: add N * logSA, write scalar output
__global__ void finish_kernel(float* out, int N) {
    const double logSA =
        lgamma(128.0) - log(2.0) - 128.0 * log(3.14159265358979323846);
    out[0] = (float)(g_acc + (double)N * logSA);
}

extern "C" void kernel_launch(void* const* d_in, const int* in_sizes, int n_in,
                              void* d_out, int out_size) {
    const float* X = nullptr;
    const float* M = nullptr;
    const float* pi = nullptr;
    int N = 0;
    for (int i = 0; i < n_in; ++i) {
        int sz = in_sizes[i];
        if (sz == KK) pi = (const float*)d_in[i];
        else if (sz == KK * PP * RR) M = (const float*)d_in[i];
        else { X = (const float*)d_in[i]; N = sz / PP; }
    }

    prep1_kernel<<<KK, 256>>>(M);
    prep2_kernel<<<1, KK>>>(pi);
    int nb = (N + NT - 1) / NT;
    main_kernel<<<nb, 512>>>(X, N);
    finish_kernel<<<1, 1>>>((float*)d_out, N);
}

// round 4
// speedup vs baseline: 6.6909x; 6.6909x over previous
#include <cuda_runtime.h>
#include <cuda_bf16.h>
#include <math.h>
#include <stdint.h>

#define KK 64
#define PP 256
#define RR 16
#define MROWS 128                       // rows per CTA

// smem: X tile 64KB | B pass tile 64KB | reduction 512B
#define SMO_X 0
#define SMO_B 65536
#define SMO_RED 131072
#define SMEM_TOTAL (131072 + 512)

// ---- device globals (no allocation allowed) ----
__device__ __align__(16) __nv_bfloat16 g_B[KK * RR * PP];  // [j][p] (= [n][k] col-major B)
__device__ float  g_w[KK];              // exp(c_k - cmax)
__device__ float  g_logdet[KK];
__device__ float  g_cshift;
__device__ double g_acc;

// ================= helpers =================
__device__ __forceinline__ uint32_t smem_u32(const void* p) {
    uint32_t a;
    asm("{ .reg .u64 t; cvta.to.shared.u64 t, %1; cvt.u32.u64 %0, t; }"
        : "=r"(a) : "l"(p));
    return a;
}
__device__ __forceinline__ void ldsm4(uint32_t* r, uint32_t addr) {
    asm volatile("ldmatrix.sync.aligned.m8n8.x4.shared.b16 {%0,%1,%2,%3}, [%4];"
                 : "=r"(r[0]), "=r"(r[1]), "=r"(r[2]), "=r"(r[3]) : "r"(addr));
}
__device__ __forceinline__ void mma16816(float* c, const uint32_t* a,
                                         uint32_t b0, uint32_t b1) {
    asm volatile(
        "mma.sync.aligned.m16n8k16.row.col.f32.bf16.bf16.f32 "
        "{%0,%1,%2,%3}, {%4,%5,%6,%7}, {%8,%9}, {%0,%1,%2,%3};"
        : "+f"(c[0]), "+f"(c[1]), "+f"(c[2]), "+f"(c[3])
        : "r"(a[0]), "r"(a[1]), "r"(a[2]), "r"(a[3]), "r"(b0), "r"(b1));
}

// ================= prep1: per-k Cholesky of I+M^T M, logdet, B = (M L^{-T})^T bf16 ======
__global__ void prep1_kernel(const float* __restrict__ M) {
    __shared__ float sM[PP * RR];
    __shared__ float sD[RR][RR + 1];
    const int k = blockIdx.x;
    const int tid = threadIdx.x;      // 256

    const float4* Mg = (const float4*)(M + (size_t)k * PP * RR);
    float4* sM4 = (float4*)sM;
#pragma unroll
    for (int i = 0; i < 4; ++i) sM4[tid + i * 256] = Mg[tid + i * 256];
    __syncthreads();

    {
        int r = tid >> 4, s = tid & 15;
        float d = (r == s) ? 1.0f : 0.0f;
        for (int p = 0; p < PP; ++p) d += sM[p * RR + r] * sM[p * RR + s];
        sD[r][s] = d;
    }
    __syncthreads();

    if (tid == 0) {
        float logdet = 0.f;
        for (int j = 0; j < RR; ++j) {
            float sum = sD[j][j];
            for (int t = 0; t < j; ++t) sum -= sD[j][t] * sD[j][t];
            float Ljj = sqrtf(sum);
            sD[j][j] = Ljj;
            logdet += 2.0f * logf(Ljj);
            float inv = 1.0f / Ljj;
            for (int i = j + 1; i < RR; ++i) {
                float s2 = sD[i][j];
                for (int t = 0; t < j; ++t) s2 -= sD[i][t] * sD[j][t];
                sD[i][j] = s2 * inv;
            }
        }
        g_logdet[k] = logdet;
    }
    __syncthreads();

    {   // forward solve L y = m_p for each row p; scatter bf16 to g_B[(k*16+i)*256 + p]
        const int p = tid;
        float y[RR];
#pragma unroll
        for (int i = 0; i < RR; ++i) {
            float s2 = sM[p * RR + i];
#pragma unroll
            for (int j = 0; j < RR; ++j)
                if (j < i) s2 -= sD[i][j] * y[j];
            y[i] = s2 / sD[i][i];
        }
#pragma unroll
        for (int i = 0; i < RR; ++i)
            g_B[(size_t)(k * RR + i) * PP + p] = __float2bfloat16(y[i]);
    }
}

// ================= prep2: w_k = exp(c_k - cmax) =================
__global__ void prep2_kernel(const float* __restrict__ pi) {
    __shared__ float sc[KK];
    __shared__ float lse_s, cmax_s;
    const int t = threadIdx.x;        // 64
    sc[t] = pi[t];
    __syncthreads();
    if (t == 0) {
        float m = sc[0];
        for (int i = 1; i < KK; ++i) m = fmaxf(m, sc[i]);
        float s = 0.f;
        for (int i = 0; i < KK; ++i) s += expf(sc[i] - m);
        lse_s = m + logf(s);
        g_acc = 0.0;
    }
    __syncthreads();
    float c = (sc[t] - lse_s) - 0.5f * g_logdet[t];
    sc[t] = c;
    __syncthreads();
    if (t == 0) {
        float m = sc[0];
        for (int i = 1; i < KK; ++i) m = fmaxf(m, sc[i]);
        cmax_s = m;
        g_cshift = m;
    }
    __syncthreads();
    g_w[t] = expf(c - cmax_s);
}

// ================= main: bf16 mma.sync GEMM + fused ACG epilogue =================
// 256 thr = 8 warps. Warp w: rows 32*(w&3)..+31 (2 m16 tiles), comps 4*(w>>2)..+3 per pass.
__global__ void __launch_bounds__(256, 1)
main_mma_kernel(const float* __restrict__ X, int N) {
    extern __shared__ char smem[];
    char* sX = smem + SMO_X;
    char* sB = smem + SMO_B;
    float* sRed = (float*)(smem + SMO_RED);

    const int tid = threadIdx.x;
    const int w = tid >> 5, l = tid & 31;
    const int base = blockIdx.x * MROWS;

    if (tid < 128) sRed[tid] = 0.f;

    // ---- load X tile (128 x 256 fp32 -> bf16), crosswise swizzle ----
#pragma unroll 4
    for (int i = 0; i < 32; ++i) {
        int u = tid + i * 256;              // 0..8191 float4s
        int row = u >> 6, c4 = u & 63;
        int n = base + row; if (n > N - 1) n = N - 1;
        float4 v = *(const float4*)(X + (size_t)n * PP + c4 * 4);
        __nv_bfloat162 lo = __floats2bfloat162_rn(v.x, v.y);
        __nv_bfloat162 hi = __floats2bfloat162_rn(v.z, v.w);
        uint2 val;
        val.x = *(uint32_t*)&lo;
        val.y = *(uint32_t*)&hi;
        int col = c4 * 4;
        uint32_t byte = (uint32_t)row * 512u
                      + (uint32_t)((((col >> 3) ^ (row & 7)) << 4) + (col & 7) * 2);
        *(uint2*)(sX + byte) = val;
    }

    const uint32_t sbX = smem_u32(sX);
    const uint32_t sbB = smem_u32(sB);

    // ---- per-lane ldmatrix addressing ----
    const int R0 = (w & 3) * 32;
    const int rA = R0 + (l & 7) + ((l >> 3) & 1) * 8;   // A matrices: r0-7,r8-15 @kb; then +8 cols
    const uint32_t koffA = (uint32_t)(l >> 4);          // col-group +0/+1
    const uint32_t baseA0 = sbX + (uint32_t)rA * 512u;
    const uint32_t baseA1 = baseA0 + 16u * 512u;
    const uint32_t swA = (uint32_t)(rA & 7);

    const int nIn = (l & 7) + ((l >> 4) & 1) * 8;       // B matrices: n0-7@kb, n0-7@kb+8, n8-15...
    const uint32_t koffB = (uint32_t)((l >> 3) & 1);
    const uint32_t baseB0 = sbB + (uint32_t)((w >> 2) * 64 + nIn) * 512u;
    const uint32_t swB = (uint32_t)(nIn & 7);

    float s[2][2] = {{0.f, 0.f}, {0.f, 0.f}};

    for (int cb = 0; cb < 8; ++cb) {
        __syncthreads();                                 // prev pass done reading sB
        {   // load B pass tile: j rows cb*128..+127, swizzled
            const uint4* src = (const uint4*)(g_B + (size_t)cb * 128 * PP);
#pragma unroll 4
            for (int i = 0; i < 16; ++i) {
                int u = tid + i * 256;                   // 0..4095 uint4s
                int jl = u >> 5, cg = u & 31;
                uint4 v = src[u];
                uint32_t byte = (uint32_t)jl * 512u + (uint32_t)((cg ^ (jl & 7)) << 4);
                *(uint4*)(sB + byte) = v;
            }
        }
        __syncthreads();

        float acc[2][4][2][4];
#pragma unroll
        for (int i = 0; i < 2; ++i)
#pragma unroll
            for (int c = 0; c < 4; ++c)
#pragma unroll
                for (int t = 0; t < 2; ++t)
#pragma unroll
                    for (int e = 0; e < 4; ++e) acc[i][c][t][e] = 0.f;

#pragma unroll
        for (int ks = 0; ks < 16; ++ks) {
            uint32_t a0[4], a1[4];
            uint32_t gA = ((2u * ks + koffA) ^ swA) << 4;
            ldsm4(a0, baseA0 + gA);
            ldsm4(a1, baseA1 + gA);
            uint32_t gB = ((2u * ks + koffB) ^ swB) << 4;
#pragma unroll
            for (int c = 0; c < 4; ++c) {
                uint32_t b[4];
                ldsm4(b, baseB0 + (uint32_t)c * 8192u + gB);
                mma16816(acc[0][c][0], a0, b[0], b[1]);
                mma16816(acc[0][c][1], a0, b[2], b[3]);
                mma16816(acc[1][c][0], a1, b[0], b[1]);
                mma16816(acc[1][c][1], a1, b[2], b[3]);
            }
        }

        // ---- epilogue for this pass's 4 comps ----
#pragma unroll
        for (int c = 0; c < 4; ++c) {
            const int kg = cb * 8 + (w >> 2) * 4 + c;
            const float wk = g_w[kg];
#pragma unroll
            for (int i = 0; i < 2; ++i) {
#pragma unroll
                for (int h = 0; h < 2; ++h) {
                    float q = acc[i][c][0][2 * h]     * acc[i][c][0][2 * h]
                            + acc[i][c][0][2 * h + 1] * acc[i][c][0][2 * h + 1]
                            + acc[i][c][1][2 * h]     * acc[i][c][1][2 * h]
                            + acc[i][c][1][2 * h + 1] * acc[i][c][1][2 * h + 1];
                    q += __shfl_xor_sync(0xffffffffu, q, 1);
                    q += __shfl_xor_sync(0xffffffffu, q, 2);
                    float pdf = 1.0f - q;
                    float p2 = pdf * pdf;   // ^2
                    p2 = p2 * p2;           // ^4
                    p2 = p2 * p2;           // ^8
                    p2 = p2 * p2;           // ^16
                    p2 = p2 * p2;           // ^32
                    p2 = p2 * p2;           // ^64
                    p2 = p2 * p2;           // ^128
                    s[i][h] += __fdividef(wk, p2);
                }
            }
        }
    }

    // ---- combine the two comp-halves (warps w and w+4 share rows) ----
    if ((l & 3) == 0) {
        int g = l >> 2;
#pragma unroll
        for (int i = 0; i < 2; ++i)
#pragma unroll
            for (int h = 0; h < 2; ++h)
                atomicAdd(&sRed[R0 + 16 * i + 8 * h + g], s[i][h]);
    }
    __syncthreads();

    float val = 0.f;
    if (tid < 128) {
        int n = base + tid;
        val = (n < N) ? logf(sRed[tid]) : 0.f;
    }
    __syncthreads();
#pragma unroll
    for (int o = 16; o > 0; o >>= 1) val += __shfl_xor_sync(0xffffffffu, val, o);
    if (l == 0) sRed[w] = val;
    __syncthreads();
    if (tid == 0) {
        float bs = 0.f;
#pragma unroll
        for (int i = 0; i < 8; ++i) bs += sRed[i];
        atomicAdd(&g_acc, (double)bs);
    }
}

// ================= finish =================
__global__ void finish_kernel(float* out, int N) {
    const double logSA =
        lgamma(128.0) - log(2.0) - 128.0 * log(3.14159265358979323846);
    out[0] = (float)(g_acc + (double)N * (logSA + (double)g_cshift));
}

extern "C" void kernel_launch(void* const* d_in, const int* in_sizes, int n_in,
                              void* d_out, int out_size) {
    const float* X = nullptr;
    const float* M = nullptr;
    const float* pi = nullptr;
    int N = 0;
    for (int i = 0; i < n_in; ++i) {
        int sz = in_sizes[i];
        if (sz == KK) pi = (const float*)d_in[i];
        else if (sz == KK * PP * RR) M = (const float*)d_in[i];
        else { X = (const float*)d_in[i]; N = sz / PP; }
    }

    static bool attr_done = false;
    if (!attr_done) {
        cudaFuncSetAttribute(main_mma_kernel,
                             cudaFuncAttributeMaxDynamicSharedMemorySize, SMEM_TOTAL);
        attr_done = true;
    }

    prep1_kernel<<<KK, 256>>>(M);
    prep2_kernel<<<1, KK>>>(pi);
    int nb = (N + MROWS - 1) / MROWS;
    main_mma_kernel<<<nb, 256, SMEM_TOTAL>>>(X, N);
    finish_kernel<<<1, 1>>>((float*)d_out, N);
}

// round 6
// speedup vs baseline: 7.7188x; 1.1536x over previous
#include <cuda_runtime.h>
#include <cuda_bf16.h>
#include <math.h>
#include <stdint.h>

#define KK 64
#define PP 256
#define RR 16
#define MROWS 128                       // rows per CTA

// smem: X tile 64KB | B stage0 64KB | B stage1 64KB | reduction 512B
#define SMO_X 0
#define SMO_B0 65536
#define SMO_B1 131072
#define SMO_RED 196608
#define SMEM_TOTAL (196608 + 512)

// ---- device globals (no allocation allowed) ----
__device__ __align__(16) __nv_bfloat16 g_B[KK * RR * PP];  // [j][p] (= [n][k] col-major B)
__device__ float  g_w[KK];              // exp(c_k - cmax)
__device__ float  g_logdet[KK];
__device__ float  g_cshift;
__device__ double g_acc;

// ================= helpers =================
__device__ __forceinline__ uint32_t smem_u32(const void* p) {
    uint32_t a;
    asm("{ .reg .u64 t; cvta.to.shared.u64 t, %1; cvt.u32.u64 %0, t; }"
        : "=r"(a) : "l"(p));
    return a;
}
__device__ __forceinline__ void ldsm4(uint32_t* r, uint32_t addr) {
    asm volatile("ldmatrix.sync.aligned.m8n8.x4.shared.b16 {%0,%1,%2,%3}, [%4];"
                 : "=r"(r[0]), "=r"(r[1]), "=r"(r[2]), "=r"(r[3]) : "r"(addr));
}
__device__ __forceinline__ void mma16816(float* c, const uint32_t* a,
                                         uint32_t b0, uint32_t b1) {
    asm volatile(
        "mma.sync.aligned.m16n8k16.row.col.f32.bf16.bf16.f32 "
        "{%0,%1,%2,%3}, {%4,%5,%6,%7}, {%8,%9}, {%0,%1,%2,%3};"
        : "+f"(c[0]), "+f"(c[1]), "+f"(c[2]), "+f"(c[3])
        : "r"(a[0]), "r"(a[1]), "r"(a[2]), "r"(a[3]), "r"(b0), "r"(b1));
}
__device__ __forceinline__ void cp16(uint32_t dst, const void* src) {
    asm volatile("cp.async.cg.shared.global [%0], [%1], 16;"
                 :: "r"(dst), "l"(src) : "memory");
}
__device__ __forceinline__ void cp_commit() {
    asm volatile("cp.async.commit_group;" ::: "memory");
}
template <int NN>
__device__ __forceinline__ void cp_wait() {
    asm volatile("cp.async.wait_group %0;" :: "n"(NN) : "memory");
}

// ================= prep1: per-k Cholesky of I+M^T M, logdet, B = (M L^{-T})^T bf16 ======
__global__ void prep1_kernel(const float* __restrict__ M) {
    __shared__ float sM[PP * RR];
    __shared__ float sD[RR][RR + 1];
    const int k = blockIdx.x;
    const int tid = threadIdx.x;      // 256

    const float4* Mg = (const float4*)(M + (size_t)k * PP * RR);
    float4* sM4 = (float4*)sM;
#pragma unroll
    for (int i = 0; i < 4; ++i) sM4[tid + i * 256] = Mg[tid + i * 256];
    __syncthreads();

    {
        int r = tid >> 4, s = tid & 15;
        float d = (r == s) ? 1.0f : 0.0f;
        for (int p = 0; p < PP; ++p) d += sM[p * RR + r] * sM[p * RR + s];
        sD[r][s] = d;
    }
    __syncthreads();

    if (tid == 0) {
        float logdet = 0.f;
        for (int j = 0; j < RR; ++j) {
            float sum = sD[j][j];
            for (int t = 0; t < j; ++t) sum -= sD[j][t] * sD[j][t];
            float Ljj = sqrtf(sum);
            sD[j][j] = Ljj;
            logdet += 2.0f * logf(Ljj);
            float inv = 1.0f / Ljj;
            for (int i = j + 1; i < RR; ++i) {
                float s2 = sD[i][j];
                for (int t = 0; t < j; ++t) s2 -= sD[i][t] * sD[j][t];
                sD[i][j] = s2 * inv;
            }
        }
        g_logdet[k] = logdet;
    }
    __syncthreads();

    {   // forward solve L y = m_p for each row p; scatter bf16 to g_B[(k*16+i)*256 + p]
        const int p = tid;
        float y[RR];
#pragma unroll
        for (int i = 0; i < RR; ++i) {
            float s2 = sM[p * RR + i];
#pragma unroll
            for (int j = 0; j < RR; ++j)
                if (j < i) s2 -= sD[i][j] * y[j];
            y[i] = s2 / sD[i][i];
        }
#pragma unroll
        for (int i = 0; i < RR; ++i)
            g_B[(size_t)(k * RR + i) * PP + p] = __float2bfloat16(y[i]);
    }
}

// ================= prep2: w_k = exp(c_k - cmax) =================
__global__ void prep2_kernel(const float* __restrict__ pi) {
    __shared__ float sc[KK];
    __shared__ float lse_s, cmax_s;
    const int t = threadIdx.x;        // 64
    sc[t] = pi[t];
    __syncthreads();
    if (t == 0) {
        float m = sc[0];
        for (int i = 1; i < KK; ++i) m = fmaxf(m, sc[i]);
        float s = 0.f;
        for (int i = 0; i < KK; ++i) s += expf(sc[i] - m);
        lse_s = m + logf(s);
        g_acc = 0.0;
    }
    __syncthreads();
    float c = (sc[t] - lse_s) - 0.5f * g_logdet[t];
    sc[t] = c;
    __syncthreads();
    if (t == 0) {
        float m = sc[0];
        for (int i = 1; i < KK; ++i) m = fmaxf(m, sc[i]);
        cmax_s = m;
        g_cshift = m;
    }
    __syncthreads();
    g_w[t] = expf(c - cmax_s);
}

// ================= main: bf16 mma.sync GEMM + fused ACG epilogue =================
// 256 thr = 8 warps. Warp w: rows 32*(w&3)..+31 (2 m16 tiles), comps 4*(w>>2)..+3 per pass.
// B pass tiles double-buffered via cp.async (stage = cb&1).
__global__ void __launch_bounds__(256, 1)
main_mma_kernel(const float* __restrict__ X, int N) {
    extern __shared__ char smem[];
    char* sX = smem + SMO_X;
    float* sRed = (float*)(smem + SMO_RED);

    const int tid = threadIdx.x;
    const int w = tid >> 5, l = tid & 31;
    const int base = blockIdx.x * MROWS;

    const uint32_t sbX = smem_u32(sX);
    const uint32_t sbB0 = smem_u32(smem + SMO_B0);

    // per-thread cp.async addressing for a B pass tile (16 uint4 each)
    uint32_t bDst[16];
    const char* bSrc[16];
#pragma unroll
    for (int i = 0; i < 16; ++i) {
        int u = tid + i * 256;                 // 0..4095 uint4s
        int jl = u >> 5, cg = u & 31;
        bDst[i] = (uint32_t)jl * 512u + (uint32_t)((cg ^ (jl & 7)) << 4);
        bSrc[i] = (const char*)g_B + (size_t)u * 16;
    }

    // prefetch B pass 0 into stage 0 (streams under the X load below)
#pragma unroll
    for (int i = 0; i < 16; ++i) cp16(sbB0 + bDst[i], bSrc[i]);
    cp_commit();

    if (tid < 128) sRed[tid] = 0.f;

    // ---- load X tile (128 x 256 fp32 -> bf16), crosswise swizzle ----
#pragma unroll 4
    for (int i = 0; i < 32; ++i) {
        int u = tid + i * 256;              // 0..8191 float4s
        int row = u >> 6, c4 = u & 63;
        int n = base + row; if (n > N - 1) n = N - 1;
        float4 v = *(const float4*)(X + (size_t)n * PP + c4 * 4);
        __nv_bfloat162 lo = __floats2bfloat162_rn(v.x, v.y);
        __nv_bfloat162 hi = __floats2bfloat162_rn(v.z, v.w);
        uint2 val;
        val.x = *(uint32_t*)&lo;
        val.y = *(uint32_t*)&hi;
        int col = c4 * 4;
        uint32_t byte = (uint32_t)row * 512u
                      + (uint32_t)((((col >> 3) ^ (row & 7)) << 4) + (col & 7) * 2);
        *(uint2*)(sX + byte) = val;
    }

    // ---- per-lane ldmatrix addressing ----
    const int R0 = (w & 3) * 32;
    const int rA = R0 + (l & 7) + ((l >> 3) & 1) * 8;   // A matrices: r0-7,r8-15 @kb; then +8 cols
    const uint32_t koffA = (uint32_t)(l >> 4);          // col-group +0/+1
    const uint32_t baseA0 = sbX + (uint32_t)rA * 512u;
    const uint32_t baseA1 = baseA0 + 16u * 512u;
    const uint32_t swA = (uint32_t)(rA & 7);

    const int nIn = (l & 7) + ((l >> 4) & 1) * 8;       // B matrices: n0-7@kb, n0-7@kb+8, n8-15...
    const uint32_t koffB = (uint32_t)((l >> 3) & 1);
    const uint32_t bWarpOff = (uint32_t)((w >> 2) * 64 + nIn) * 512u;
    const uint32_t swB = (uint32_t)(nIn & 7);

    float s[2][2] = {{0.f, 0.f}, {0.f, 0.f}};

    for (int cb = 0; cb < 8; ++cb) {
        __syncthreads();     // X ready (cb=0) / all warps done reading stage (cb+1)&1 (cb>0)

        if (cb + 1 < 8) {    // prefetch next pass into the other stage
            const uint32_t sbNext = sbB0 + (uint32_t)((cb + 1) & 1) * 65536u;
            const size_t srcOff = (size_t)(cb + 1) * 65536;   // 128 j-rows * 512 B
#pragma unroll
            for (int i = 0; i < 16; ++i) cp16(sbNext + bDst[i], bSrc[i] + srcOff);
            cp_commit();
            cp_wait<1>();    // current pass's B has landed
        } else {
            cp_wait<0>();
        }
        __syncthreads();     // B(cb) visible to all threads

        const uint32_t baseB0 = sbB0 + (uint32_t)(cb & 1) * 65536u + bWarpOff;

        float acc[2][4][2][4];
#pragma unroll
        for (int i = 0; i < 2; ++i)
#pragma unroll
            for (int c = 0; c < 4; ++c)
#pragma unroll
                for (int t = 0; t < 2; ++t)
#pragma unroll
                    for (int e = 0; e < 4; ++e) acc[i][c][t][e] = 0.f;

#pragma unroll
        for (int ks = 0; ks < 16; ++ks) {
            uint32_t a0[4], a1[4];
            uint32_t gA = ((2u * ks + koffA) ^ swA) << 4;
            ldsm4(a0, baseA0 + gA);
            ldsm4(a1, baseA1 + gA);
            uint32_t gB = ((2u * ks + koffB) ^ swB) << 4;
#pragma unroll
            for (int c = 0; c < 4; ++c) {
                uint32_t b[4];
                ldsm4(b, baseB0 + (uint32_t)c * 8192u + gB);
                mma16816(acc[0][c][0], a0, b[0], b[1]);
                mma16816(acc[0][c][1], a0, b[2], b[3]);
                mma16816(acc[1][c][0], a1, b[0], b[1]);
                mma16816(acc[1][c][1], a1, b[2], b[3]);
            }
        }

        // ---- epilogue for this pass's 4 comps ----
#pragma unroll
        for (int c = 0; c < 4; ++c) {
            const int kg = cb * 8 + (w >> 2) * 4 + c;
            const float wk = g_w[kg];
#pragma unroll
            for (int i = 0; i < 2; ++i) {
#pragma unroll
                for (int h = 0; h < 2; ++h) {
                    float q = acc[i][c][0][2 * h]     * acc[i][c][0][2 * h]
                            + acc[i][c][0][2 * h + 1] * acc[i][c][0][2 * h + 1]
                            + acc[i][c][1][2 * h]     * acc[i][c][1][2 * h]
                            + acc[i][c][1][2 * h + 1] * acc[i][c][1][2 * h + 1];
                    q += __shfl_xor_sync(0xffffffffu, q, 1);
                    q += __shfl_xor_sync(0xffffffffu, q, 2);
                    float pdf = 1.0f - q;
                    float p2 = pdf * pdf;   // ^2
                    p2 = p2 * p2;           // ^4
                    p2 = p2 * p2;           // ^8
                    p2 = p2 * p2;           // ^16
                    p2 = p2 * p2;           // ^32
                    p2 = p2 * p2;           // ^64
                    p2 = p2 * p2;           // ^128
                    s[i][h] += __fdividef(wk, p2);
                }
            }
        }
    }

    // ---- combine the two comp-halves (warps w and w+4 share rows) ----
    if ((l & 3) == 0) {
        int g = l >> 2;
#pragma unroll
        for (int i = 0; i < 2; ++i)
#pragma unroll
            for (int h = 0; h < 2; ++h)
                atomicAdd(&sRed[R0 + 16 * i + 8 * h + g], s[i][h]);
    }
    __syncthreads();

    float val = 0.f;
    if (tid < 128) {
        int n = base + tid;
        val = (n < N) ? logf(sRed[tid]) : 0.f;
    }
    __syncthreads();
#pragma unroll
    for (int o = 16; o > 0; o >>= 1) val += __shfl_xor_sync(0xffffffffu, val, o);
    if (l == 0) sRed[w] = val;
    __syncthreads();
    if (tid == 0) {
        float bs = 0.f;
#pragma unroll
        for (int i = 0; i < 8; ++i) bs += sRed[i];
        atomicAdd(&g_acc, (double)bs);
    }
}

// ================= finish =================
__global__ void finish_kernel(float* out, int N) {
    const double logSA =
        lgamma(128.0) - log(2.0) - 128.0 * log(3.14159265358979323846);
    out[0] = (float)(g_acc + (double)N * (logSA + (double)g_cshift));
}

extern "C" void kernel_launch(void* const* d_in, const int* in_sizes, int n_in,
                              void* d_out, int out_size) {
    const float* X = nullptr;
    const float* M = nullptr;
    const float* pi = nullptr;
    int N = 0;
    for (int i = 0; i < n_in; ++i) {
        int sz = in_sizes[i];
        if (sz == KK) pi = (const float*)d_in[i];
        else if (sz == KK * PP * RR) M = (const float*)d_in[i];
        else { X = (const float*)d_in[i]; N = sz / PP; }
    }

    static bool attr_done = false;
    if (!attr_done) {
        cudaFuncSetAttribute(main_mma_kernel,
                             cudaFuncAttributeMaxDynamicSharedMemorySize, SMEM_TOTAL);
        attr_done = true;
    }

    prep1_kernel<<<KK, 256>>>(M);
    prep2_kernel<<<1, KK>>>(pi);
    int nb = (N + MROWS - 1) / MROWS;
    main_mma_kernel<<<nb, 256, SMEM_TOTAL>>>(X, N);
    finish_kernel<<<1, 1>>>((float*)d_out, N);
}

// round 7
// speedup vs baseline: 7.7906x; 1.0093x over previous
#include <cuda_runtime.h>
#include <cuda_bf16.h>
#include <math.h>
#include <stdint.h>

#define KK 64
#define PP 256
#define RR 16
#define MROWS 128                       // rows per CTA

// smem: X tile 64KB | B stage0 64KB | B stage1 64KB | red 512B | w 256B | meta 16B
#define SMO_X 0
#define SMO_B0 65536
#define SMO_B1 131072
#define SMO_RED 196608
#define SMO_W   (196608 + 512)
#define SMO_META (196608 + 512 + 256)
#define SMEM_TOTAL (196608 + 1024)

// ---- device globals (no allocation allowed) ----
__device__ __align__(16) __nv_bfloat16 g_B[KK * RR * PP];  // [j][p] (= [n][k] col-major B)
__device__ float  g_logdet[KK];
__device__ double g_acc;
__device__ unsigned int g_count;

// ================= helpers =================
__device__ __forceinline__ uint32_t smem_u32(const void* p) {
    uint32_t a;
    asm("{ .reg .u64 t; cvta.to.shared.u64 t, %1; cvt.u32.u64 %0, t; }"
        : "=r"(a) : "l"(p));
    return a;
}
__device__ __forceinline__ void ldsm4(uint32_t* r, uint32_t addr) {
    asm volatile("ldmatrix.sync.aligned.m8n8.x4.shared.b16 {%0,%1,%2,%3}, [%4];"
                 : "=r"(r[0]), "=r"(r[1]), "=r"(r[2]), "=r"(r[3]) : "r"(addr));
}
__device__ __forceinline__ void mma16816(float* c, const uint32_t* a,
                                         uint32_t b0, uint32_t b1) {
    asm volatile(
        "mma.sync.aligned.m16n8k16.row.col.f32.bf16.bf16.f32 "
        "{%0,%1,%2,%3}, {%4,%5,%6,%7}, {%8,%9}, {%0,%1,%2,%3};"
        : "+f"(c[0]), "+f"(c[1]), "+f"(c[2]), "+f"(c[3])
        : "r"(a[0]), "r"(a[1]), "r"(a[2]), "r"(a[3]), "r"(b0), "r"(b1));
}
__device__ __forceinline__ void cp16(uint32_t dst, const void* src) {
    asm volatile("cp.async.cg.shared.global [%0], [%1], 16;"
                 :: "r"(dst), "l"(src) : "memory");
}
__device__ __forceinline__ void cp_commit() {
    asm volatile("cp.async.commit_group;" ::: "memory");
}
template <int NN>
__device__ __forceinline__ void cp_wait() {
    asm volatile("cp.async.wait_group %0;" :: "n"(NN) : "memory");
}

// ================= prep1: per-k Cholesky of I+M^T M, logdet, B = (M L^{-T})^T bf16 ======
__global__ void prep1_kernel(const float* __restrict__ M) {
    __shared__ float sM[PP * RR];
    __shared__ float sD[RR][RR + 1];
    const int k = blockIdx.x;
    const int tid = threadIdx.x;      // 256

    if (k == 0 && tid == 0) { g_acc = 0.0; g_count = 0u; }

    const float4* Mg = (const float4*)(M + (size_t)k * PP * RR);
    float4* sM4 = (float4*)sM;
#pragma unroll
    for (int i = 0; i < 4; ++i) sM4[tid + i * 256] = Mg[tid + i * 256];
    __syncthreads();

    {
        int r = tid >> 4, s = tid & 15;
        float d = (r == s) ? 1.0f : 0.0f;
        for (int p = 0; p < PP; ++p) d += sM[p * RR + r] * sM[p * RR + s];
        sD[r][s] = d;
    }
    __syncthreads();

    if (tid == 0) {
        float logdet = 0.f;
        for (int j = 0; j < RR; ++j) {
            float sum = sD[j][j];
            for (int t = 0; t < j; ++t) sum -= sD[j][t] * sD[j][t];
            float Ljj = sqrtf(sum);
            sD[j][j] = Ljj;
            logdet += 2.0f * logf(Ljj);
            float inv = 1.0f / Ljj;
            for (int i = j + 1; i < RR; ++i) {
                float s2 = sD[i][j];
                for (int t = 0; t < j; ++t) s2 -= sD[i][t] * sD[j][t];
                sD[i][j] = s2 * inv;
            }
        }
        g_logdet[k] = logdet;
    }
    __syncthreads();

    {   // forward solve L y = m_p for each row p; scatter bf16 to g_B[(k*16+i)*256 + p]
        const int p = tid;
        float y[RR];
#pragma unroll
        for (int i = 0; i < RR; ++i) {
            float s2 = sM[p * RR + i];
#pragma unroll
            for (int j = 0; j < RR; ++j)
                if (j < i) s2 -= sD[i][j] * y[j];
            y[i] = s2 / sD[i][i];
        }
#pragma unroll
        for (int i = 0; i < RR; ++i)
            g_B[(size_t)(k * RR + i) * PP + p] = __float2bfloat16(y[i]);
    }
}

// ================= main: bf16 mma.sync GEMM + fused ACG epilogue + finalize =============
// 256 thr = 8 warps. Warp w: rows 32*(w&3)..+31 (2 m16 tiles), comps 4*(w>>2)..+3 per pass.
// B pass tiles double-buffered via cp.async (stage = cb&1). Last CTA writes the output.
__global__ void __launch_bounds__(256, 1)
main_mma_kernel(const float* __restrict__ X, const float* __restrict__ pi,
                float* __restrict__ out, int N, int nblocks) {
    extern __shared__ char smem[];
    char* sX = smem + SMO_X;
    float* sRed = (float*)(smem + SMO_RED);
    float* sW = (float*)(smem + SMO_W);
    float* sMeta = (float*)(smem + SMO_META);

    const int tid = threadIdx.x;
    const int w = tid >> 5, l = tid & 31;
    const int base = blockIdx.x * MROWS;

    const uint32_t sbX = smem_u32(sX);
    const uint32_t sbB0 = smem_u32(smem + SMO_B0);

    // per-thread cp.async addressing for a B pass tile (16 uint4 each)
    uint32_t bDst[16];
    const char* bSrc[16];
#pragma unroll
    for (int i = 0; i < 16; ++i) {
        int u = tid + i * 256;                 // 0..4095 uint4s
        int jl = u >> 5, cg = u & 31;
        bDst[i] = (uint32_t)jl * 512u + (uint32_t)((cg ^ (jl & 7)) << 4);
        bSrc[i] = (const char*)g_B + (size_t)u * 16;
    }

    // prefetch B pass 0 into stage 0 (streams under the X load below)
#pragma unroll
    for (int i = 0; i < 16; ++i) cp16(sbB0 + bDst[i], bSrc[i]);
    cp_commit();

    // ---- per-CTA mixture weights: w_k = exp(c_k - cmax), warp 0 only ----
    if (w == 0) {
        float p1 = pi[l], p2 = pi[l + 32];
        float ld1 = g_logdet[l], ld2 = g_logdet[l + 32];
        float m = fmaxf(p1, p2);
#pragma unroll
        for (int o = 16; o > 0; o >>= 1) m = fmaxf(m, __shfl_xor_sync(0xffffffffu, m, o));
        float s = expf(p1 - m) + expf(p2 - m);
#pragma unroll
        for (int o = 16; o > 0; o >>= 1) s += __shfl_xor_sync(0xffffffffu, s, o);
        float lse = m + logf(s);
        float c1 = (p1 - lse) - 0.5f * ld1;
        float c2 = (p2 - lse) - 0.5f * ld2;
        float cm = fmaxf(c1, c2);
#pragma unroll
        for (int o = 16; o > 0; o >>= 1) cm = fmaxf(cm, __shfl_xor_sync(0xffffffffu, cm, o));
        sW[l] = expf(c1 - cm);
        sW[l + 32] = expf(c2 - cm);
        if (l == 0) sMeta[0] = cm;
    }

    if (tid < 128) sRed[tid] = 0.f;

    // ---- load X tile (128 x 256 fp32 -> bf16), crosswise swizzle ----
#pragma unroll 4
    for (int i = 0; i < 32; ++i) {
        int u = tid + i * 256;              // 0..8191 float4s
        int row = u >> 6, c4 = u & 63;
        int n = base + row; if (n > N - 1) n = N - 1;
        float4 v = *(const float4*)(X + (size_t)n * PP + c4 * 4);
        __nv_bfloat162 lo = __floats2bfloat162_rn(v.x, v.y);
        __nv_bfloat162 hi = __floats2bfloat162_rn(v.z, v.w);
        uint2 val;
        val.x = *(uint32_t*)&lo;
        val.y = *(uint32_t*)&hi;
        int col = c4 * 4;
        uint32_t byte = (uint32_t)row * 512u
                      + (uint32_t)((((col >> 3) ^ (row & 7)) << 4) + (col & 7) * 2);
        *(uint2*)(sX + byte) = val;
    }

    // ---- per-lane ldmatrix addressing ----
    const int R0 = (w & 3) * 32;
    const int rA = R0 + (l & 7) + ((l >> 3) & 1) * 8;   // A matrices: r0-7,r8-15 @kb; then +8 cols
    const uint32_t koffA = (uint32_t)(l >> 4);          // col-group +0/+1
    const uint32_t baseA0 = sbX + (uint32_t)rA * 512u;
    const uint32_t baseA1 = baseA0 + 16u * 512u;
    const uint32_t swA = (uint32_t)(rA & 7);

    const int nIn = (l & 7) + ((l >> 4) & 1) * 8;       // B matrices: n0-7@kb, n0-7@kb+8, n8-15...
    const uint32_t koffB = (uint32_t)((l >> 3) & 1);
    const uint32_t bWarpOff = (uint32_t)((w >> 2) * 64 + nIn) * 512u;
    const uint32_t swB = (uint32_t)(nIn & 7);

    float s[2][2] = {{0.f, 0.f}, {0.f, 0.f}};

    for (int cb = 0; cb < 8; ++cb) {
        __syncthreads();     // X/sW ready (cb=0) / all warps done reading stage (cb+1)&1 (cb>0)

        if (cb + 1 < 8) {    // prefetch next pass into the other stage
            const uint32_t sbNext = sbB0 + (uint32_t)((cb + 1) & 1) * 65536u;
            const size_t srcOff = (size_t)(cb + 1) * 65536;   // 128 j-rows * 512 B
#pragma unroll
            for (int i = 0; i < 16; ++i) cp16(sbNext + bDst[i], bSrc[i] + srcOff);
            cp_commit();
            cp_wait<1>();    // current pass's B has landed
        } else {
            cp_wait<0>();
        }
        __syncthreads();     // B(cb) visible to all threads

        const uint32_t baseB0 = sbB0 + (uint32_t)(cb & 1) * 65536u + bWarpOff;

        float acc[2][4][2][4];
#pragma unroll
        for (int i = 0; i < 2; ++i)
#pragma unroll
            for (int c = 0; c < 4; ++c)
#pragma unroll
                for (int t = 0; t < 2; ++t)
#pragma unroll
                    for (int e = 0; e < 4; ++e) acc[i][c][t][e] = 0.f;

#pragma unroll
        for (int ks = 0; ks < 16; ++ks) {
            uint32_t a0[4], a1[4];
            uint32_t gA = ((2u * ks + koffA) ^ swA) << 4;
            ldsm4(a0, baseA0 + gA);
            ldsm4(a1, baseA1 + gA);
            uint32_t gB = ((2u * ks + koffB) ^ swB) << 4;
#pragma unroll
            for (int c = 0; c < 4; ++c) {
                uint32_t b[4];
                ldsm4(b, baseB0 + (uint32_t)c * 8192u + gB);
                mma16816(acc[0][c][0], a0, b[0], b[1]);
                mma16816(acc[0][c][1], a0, b[2], b[3]);
                mma16816(acc[1][c][0], a1, b[0], b[1]);
                mma16816(acc[1][c][1], a1, b[2], b[3]);
            }
        }

        // ---- epilogue for this pass's 4 comps ----
#pragma unroll
        for (int c = 0; c < 4; ++c) {
            const int kg = cb * 8 + (w >> 2) * 4 + c;
            const float wk = sW[kg];
#pragma unroll
            for (int i = 0; i < 2; ++i) {
#pragma unroll
                for (int h = 0; h < 2; ++h) {
                    float q = acc[i][c][0][2 * h]     * acc[i][c][0][2 * h]
                            + acc[i][c][0][2 * h + 1] * acc[i][c][0][2 * h + 1]
                            + acc[i][c][1][2 * h]     * acc[i][c][1][2 * h]
                            + acc[i][c][1][2 * h + 1] * acc[i][c][1][2 * h + 1];
                    q += __shfl_xor_sync(0xffffffffu, q, 1);
                    q += __shfl_xor_sync(0xffffffffu, q, 2);
                    float pdf = 1.0f - q;
                    float p2 = pdf * pdf;   // ^2
                    p2 = p2 * p2;           // ^4
                    p2 = p2 * p2;           // ^8
                    p2 = p2 * p2;           // ^16
                    p2 = p2 * p2;           // ^32
                    p2 = p2 * p2;           // ^64
                    p2 = p2 * p2;           // ^128
                    s[i][h] += __fdividef(wk, p2);
                }
            }
        }
    }

    // ---- combine the two comp-halves (warps w and w+4 share rows) ----
    if ((l & 3) == 0) {
        int g = l >> 2;
#pragma unroll
        for (int i = 0; i < 2; ++i)
#pragma unroll
            for (int h = 0; h < 2; ++h)
                atomicAdd(&sRed[R0 + 16 * i + 8 * h + g], s[i][h]);
    }
    __syncthreads();

    float val = 0.f;
    if (tid < 128) {
        int n = base + tid;
        val = (n < N) ? logf(sRed[tid]) : 0.f;
    }
    __syncthreads();
#pragma unroll
    for (int o = 16; o > 0; o >>= 1) val += __shfl_xor_sync(0xffffffffu, val, o);
    if (l == 0) sRed[w] = val;
    __syncthreads();
    if (tid == 0) {
        float bs = 0.f;
#pragma unroll
        for (int i = 0; i < 8; ++i) bs += sRed[i];
        atomicAdd(&g_acc, (double)bs);
        __threadfence();
        unsigned int old = atomicAdd(&g_count, 1u);
        if (old == (unsigned int)(nblocks - 1)) {
            double tot = atomicAdd(&g_acc, 0.0);
            const double logSA =
                lgamma(128.0) - log(2.0) - 128.0 * log(3.14159265358979323846);
            out[0] = (float)(tot + (double)N * (logSA + (double)sMeta[0]));
        }
    }
}

extern "C" void kernel_launch(void* const* d_in, const int* in_sizes, int n_in,
                              void* d_out, int out_size) {
    const float* X = nullptr;
    const float* M = nullptr;
    const float* pi = nullptr;
    int N = 0;
    for (int i = 0; i < n_in; ++i) {
        int sz = in_sizes[i];
        if (sz == KK) pi = (const float*)d_in[i];
        else if (sz == KK * PP * RR) M = (const float*)d_in[i];
        else { X = (const float*)d_in[i]; N = sz / PP; }
    }

    static bool attr_done = false;
    if (!attr_done) {
        cudaFuncSetAttribute(main_mma_kernel,
                             cudaFuncAttributeMaxDynamicSharedMemorySize, SMEM_TOTAL);
        attr_done = true;
    }

    prep1_kernel<<<KK, 256>>>(M);
    int nb = (N + MROWS - 1) / MROWS;
    main_mma_kernel<<<nb, 256, SMEM_TOTAL>>>(X, pi, (float*)d_out, N, nb);
}

// round 8
// speedup vs baseline: 8.5716x; 1.1003x over previous
#include <cuda_runtime.h>
#include <cuda_bf16.h>
#include <math.h>
#include <stdint.h>

#define KK 64
#define PP 256
#define RR 16
#define MROWS 256                       // rows per CTA
#define NPASS 16                        // B passes of 64 j-rows (4 comps each)

// smem: X tile 128KB | B stage0 32KB | B stage1 32KB | red 1KB | w 256B | meta 16B
#define SMO_X 0
#define SMO_B0 131072
#define SMO_B1 163840
#define SMO_RED 196608
#define SMO_W   (196608 + 1024)
#define SMO_META (196608 + 1024 + 256)
#define SMEM_TOTAL (196608 + 1024 + 256 + 16)

// ---- device globals (no allocation allowed) ----
__device__ __align__(16) __nv_bfloat16 g_B[KK * RR * PP];  // [j][p] (= [n][k] col-major B)
__device__ float  g_logdet[KK];
__device__ double g_acc;
__device__ unsigned int g_count;

// ================= helpers =================
__device__ __forceinline__ uint32_t smem_u32(const void* p) {
    uint32_t a;
    asm("{ .reg .u64 t; cvta.to.shared.u64 t, %1; cvt.u32.u64 %0, t; }"
        : "=r"(a) : "l"(p));
    return a;
}
__device__ __forceinline__ void ldsm4(uint32_t* r, uint32_t addr) {
    asm volatile("ldmatrix.sync.aligned.m8n8.x4.shared.b16 {%0,%1,%2,%3}, [%4];"
                 : "=r"(r[0]), "=r"(r[1]), "=r"(r[2]), "=r"(r[3]) : "r"(addr));
}
__device__ __forceinline__ void mma16816(float* c, const uint32_t* a,
                                         uint32_t b0, uint32_t b1) {
    asm volatile(
        "mma.sync.aligned.m16n8k16.row.col.f32.bf16.bf16.f32 "
        "{%0,%1,%2,%3}, {%4,%5,%6,%7}, {%8,%9}, {%0,%1,%2,%3};"
        : "+f"(c[0]), "+f"(c[1]), "+f"(c[2]), "+f"(c[3])
        : "r"(a[0]), "r"(a[1]), "r"(a[2]), "r"(a[3]), "r"(b0), "r"(b1));
}
__device__ __forceinline__ void cp16(uint32_t dst, const void* src) {
    asm volatile("cp.async.cg.shared.global [%0], [%1], 16;"
                 :: "r"(dst), "l"(src) : "memory");
}
__device__ __forceinline__ void cp_commit() {
    asm volatile("cp.async.commit_group;" ::: "memory");
}
template <int NN>
__device__ __forceinline__ void cp_wait() {
    asm volatile("cp.async.wait_group %0;" :: "n"(NN) : "memory");
}

// ================= prep1: per-k Cholesky of I+M^T M, logdet, B = (M L^{-T})^T bf16 ======
__global__ void prep1_kernel(const float* __restrict__ M) {
    __shared__ float sM[PP * RR];
    __shared__ float sD[RR][RR + 1];
    const int k = blockIdx.x;
    const int tid = threadIdx.x;      // 256

    if (k == 0 && tid == 0) { g_acc = 0.0; g_count = 0u; }

    const float4* Mg = (const float4*)(M + (size_t)k * PP * RR);
    float4* sM4 = (float4*)sM;
#pragma unroll
    for (int i = 0; i < 4; ++i) sM4[tid + i * 256] = Mg[tid + i * 256];
    __syncthreads();

    {
        int r = tid >> 4, s = tid & 15;
        float d = (r == s) ? 1.0f : 0.0f;
        for (int p = 0; p < PP; ++p) d += sM[p * RR + r] * sM[p * RR + s];
        sD[r][s] = d;
    }
    __syncthreads();

    if (tid == 0) {
        float logdet = 0.f;
        for (int j = 0; j < RR; ++j) {
            float sum = sD[j][j];
            for (int t = 0; t < j; ++t) sum -= sD[j][t] * sD[j][t];
            float Ljj = sqrtf(sum);
            sD[j][j] = Ljj;
            logdet += 2.0f * logf(Ljj);
            float inv = 1.0f / Ljj;
            for (int i = j + 1; i < RR; ++i) {
                float s2 = sD[i][j];
                for (int t = 0; t < j; ++t) s2 -= sD[i][t] * sD[j][t];
                sD[i][j] = s2 * inv;
            }
        }
        g_logdet[k] = logdet;
    }
    __syncthreads();

    {   // forward solve L y = m_p for each row p; scatter bf16 to g_B[(k*16+i)*256 + p]
        const int p = tid;
        float y[RR];
#pragma unroll
        for (int i = 0; i < RR; ++i) {
            float s2 = sM[p * RR + i];
#pragma unroll
            for (int j = 0; j < RR; ++j)
                if (j < i) s2 -= sD[i][j] * y[j];
            y[i] = s2 / sD[i][i];
        }
#pragma unroll
        for (int i = 0; i < RR; ++i)
            g_B[(size_t)(k * RR + i) * PP + p] = __float2bfloat16(y[i]);
    }
}

// ================= main: bf16 mma.sync GEMM + fused ACG epilogue + finalize =============
// 512 thr = 16 warps. Warp w: rows 32*(w&7)..+31 (2 m16 tiles), comps (pass*4 + (w>>3)*2 .. +1).
// B pass = 64 j-rows (32KB), double-buffered via cp.async (stage = cb&1). Last CTA writes out.
__global__ void __launch_bounds__(512, 1)
main_mma_kernel(const float* __restrict__ X, const float* __restrict__ pi,
                float* __restrict__ out, int N, int nblocks) {
    extern __shared__ char smem[];
    char* sX = smem + SMO_X;
    float* sRed = (float*)(smem + SMO_RED);
    float* sW = (float*)(smem + SMO_W);
    float* sMeta = (float*)(smem + SMO_META);

    const int tid = threadIdx.x;
    const int w = tid >> 5, l = tid & 31;
    const int base = blockIdx.x * MROWS;

    const uint32_t sbX = smem_u32(sX);
    const uint32_t sbB0 = smem_u32(smem + SMO_B0);

    // per-thread cp.async addressing for a 64-row B pass tile (4 uint4 each)
    uint32_t bDst[4];
    const char* bSrc[4];
#pragma unroll
    for (int i = 0; i < 4; ++i) {
        int u = tid + i * 512;                 // 0..2047 uint4s
        int jl = u >> 5, cg = u & 31;
        bDst[i] = (uint32_t)jl * 512u + (uint32_t)((cg ^ (jl & 7)) << 4);
        bSrc[i] = (const char*)g_B + (size_t)u * 16;
    }

    // prefetch B pass 0 into stage 0 (streams under the X load below)
#pragma unroll
    for (int i = 0; i < 4; ++i) cp16(sbB0 + bDst[i], bSrc[i]);
    cp_commit();

    // ---- per-CTA mixture weights: w_k = exp(c_k - cmax), warp 0 only ----
    if (w == 0) {
        float p1 = pi[l], p2 = pi[l + 32];
        float ld1 = g_logdet[l], ld2 = g_logdet[l + 32];
        float m = fmaxf(p1, p2);
#pragma unroll
        for (int o = 16; o > 0; o >>= 1) m = fmaxf(m, __shfl_xor_sync(0xffffffffu, m, o));
        float s = expf(p1 - m) + expf(p2 - m);
#pragma unroll
        for (int o = 16; o > 0; o >>= 1) s += __shfl_xor_sync(0xffffffffu, s, o);
        float lse = m + logf(s);
        float c1 = (p1 - lse) - 0.5f * ld1;
        float c2 = (p2 - lse) - 0.5f * ld2;
        float cm = fmaxf(c1, c2);
#pragma unroll
        for (int o = 16; o > 0; o >>= 1) cm = fmaxf(cm, __shfl_xor_sync(0xffffffffu, cm, o));
        sW[l] = expf(c1 - cm);
        sW[l + 32] = expf(c2 - cm);
        if (l == 0) sMeta[0] = cm;
    }

    if (tid < 256) sRed[tid] = 0.f;

    // ---- load X tile (256 x 256 fp32 -> bf16), crosswise swizzle ----
#pragma unroll 4
    for (int i = 0; i < 32; ++i) {
        int u = tid + i * 512;              // 0..16383 float4s
        int row = u >> 6, c4 = u & 63;
        int n = base + row; if (n > N - 1) n = N - 1;
        float4 v = *(const float4*)(X + (size_t)n * PP + c4 * 4);
        __nv_bfloat162 lo = __floats2bfloat162_rn(v.x, v.y);
        __nv_bfloat162 hi = __floats2bfloat162_rn(v.z, v.w);
        uint2 val;
        val.x = *(uint32_t*)&lo;
        val.y = *(uint32_t*)&hi;
        int col = c4 * 4;
        uint32_t byte = (uint32_t)row * 512u
                      + (uint32_t)((((col >> 3) ^ (row & 7)) << 4) + (col & 7) * 2);
        *(uint2*)(sX + byte) = val;
    }

    // ---- per-lane ldmatrix addressing ----
    const int R0 = (w & 7) * 32;
    const int rA = R0 + (l & 7) + ((l >> 3) & 1) * 8;   // A matrices: r0-7,r8-15 @kb; then +8 cols
    const uint32_t koffA = (uint32_t)(l >> 4);          // col-group +0/+1
    const uint32_t baseA0 = sbX + (uint32_t)rA * 512u;
    const uint32_t baseA1 = baseA0 + 16u * 512u;
    const uint32_t swA = (uint32_t)(rA & 7);

    const int cgrp = w >> 3;                            // comp-group 0/1 within pass
    const int nIn = (l & 7) + ((l >> 4) & 1) * 8;       // B matrices: n0-7@kb, n0-7@kb+8, n8-15...
    const uint32_t koffB = (uint32_t)((l >> 3) & 1);
    const uint32_t bWarpOff = (uint32_t)(cgrp * 32 + nIn) * 512u;
    const uint32_t swB = (uint32_t)(nIn & 7);

    float s[2][2] = {{0.f, 0.f}, {0.f, 0.f}};

    for (int cb = 0; cb < NPASS; ++cb) {
        __syncthreads();     // X/sW ready (cb=0) / all warps done reading stage (cb+1)&1 (cb>0)

        if (cb + 1 < NPASS) {    // prefetch next pass into the other stage
            const uint32_t sbNext = sbB0 + (uint32_t)((cb + 1) & 1) * 32768u;
            const size_t srcOff = (size_t)(cb + 1) * 32768;   // 64 j-rows * 512 B
#pragma unroll
            for (int i = 0; i < 4; ++i) cp16(sbNext + bDst[i], bSrc[i] + srcOff);
            cp_commit();
            cp_wait<1>();    // current pass's B has landed
        } else {
            cp_wait<0>();
        }
        __syncthreads();     // B(cb) visible to all threads

        const uint32_t baseB0 = sbB0 + (uint32_t)(cb & 1) * 32768u + bWarpOff;

        float acc[2][2][2][4];
#pragma unroll
        for (int i = 0; i < 2; ++i)
#pragma unroll
            for (int c = 0; c < 2; ++c)
#pragma unroll
                for (int t = 0; t < 2; ++t)
#pragma unroll
                    for (int e = 0; e < 4; ++e) acc[i][c][t][e] = 0.f;

#pragma unroll
        for (int ks = 0; ks < 16; ++ks) {
            uint32_t a0[4], a1[4];
            uint32_t gA = ((2u * ks + koffA) ^ swA) << 4;
            ldsm4(a0, baseA0 + gA);
            ldsm4(a1, baseA1 + gA);
            uint32_t gB = ((2u * ks + koffB) ^ swB) << 4;
#pragma unroll
            for (int c = 0; c < 2; ++c) {
                uint32_t b[4];
                ldsm4(b, baseB0 + (uint32_t)c * 8192u + gB);
                mma16816(acc[0][c][0], a0, b[0], b[1]);
                mma16816(acc[0][c][1], a0, b[2], b[3]);
                mma16816(acc[1][c][0], a1, b[0], b[1]);
                mma16816(acc[1][c][1], a1, b[2], b[3]);
            }
        }

        // ---- epilogue for this warp's 2 comps of the pass ----
#pragma unroll
        for (int c = 0; c < 2; ++c) {
            const int kg = cb * 4 + cgrp * 2 + c;
            const float wk = sW[kg];
#pragma unroll
            for (int i = 0; i < 2; ++i) {
#pragma unroll
                for (int h = 0; h < 2; ++h) {
                    float q = acc[i][c][0][2 * h]     * acc[i][c][0][2 * h]
                            + acc[i][c][0][2 * h + 1] * acc[i][c][0][2 * h + 1]
                            + acc[i][c][1][2 * h]     * acc[i][c][1][2 * h]
                            + acc[i][c][1][2 * h + 1] * acc[i][c][1][2 * h + 1];
                    q += __shfl_xor_sync(0xffffffffu, q, 1);
                    q += __shfl_xor_sync(0xffffffffu, q, 2);
                    float pdf = 1.0f - q;
                    float p2 = pdf * pdf;   // ^2
                    p2 = p2 * p2;           // ^4
                    p2 = p2 * p2;           // ^8
                    p2 = p2 * p2;           // ^16
                    p2 = p2 * p2;           // ^32
                    p2 = p2 * p2;           // ^64
                    p2 = p2 * p2;           // ^128
                    s[i][h] += __fdividef(wk, p2);
                }
            }
        }
    }

    // ---- combine the two comp-halves (warps w and w+8 share rows) ----
    if ((l & 3) == 0) {
        int g = l >> 2;
#pragma unroll
        for (int i = 0; i < 2; ++i)
#pragma unroll
            for (int h = 0; h < 2; ++h)
                atomicAdd(&sRed[R0 + 16 * i + 8 * h + g], s[i][h]);
    }
    __syncthreads();

    float val = 0.f;
    if (tid < 256) {
        int n = base + tid;
        val = (n < N) ? logf(sRed[tid]) : 0.f;
    }
    __syncthreads();
#pragma unroll
    for (int o = 16; o > 0; o >>= 1) val += __shfl_xor_sync(0xffffffffu, val, o);
    if (l == 0) sRed[w] = val;
    __syncthreads();
    if (tid == 0) {
        float bs = 0.f;
#pragma unroll
        for (int i = 0; i < 16; ++i) bs += sRed[i];
        atomicAdd(&g_acc, (double)bs);
        __threadfence();
        unsigned int old = atomicAdd(&g_count, 1u);
        if (old == (unsigned int)(nblocks - 1)) {
            double tot = atomicAdd(&g_acc, 0.0);
            const double logSA =
                lgamma(128.0) - log(2.0) - 128.0 * log(3.14159265358979323846);
            out[0] = (float)(tot + (double)N * (logSA + (double)sMeta[0]));
        }
    }
}

extern "C" void kernel_launch(void* const* d_in, const int* in_sizes, int n_in,
                              void* d_out, int out_size) {
    const float* X = nullptr;
    const float* M = nullptr;
    const float* pi = nullptr;
    int N = 0;
    for (int i = 0; i < n_in; ++i) {
        int sz = in_sizes[i];
        if (sz == KK) pi = (const float*)d_in[i];
        else if (sz == KK * PP * RR) M = (const float*)d_in[i];
        else { X = (const float*)d_in[i]; N = sz / PP; }
    }

    static bool attr_done = false;
    if (!attr_done) {
        cudaFuncSetAttribute(main_mma_kernel,
                             cudaFuncAttributeMaxDynamicSharedMemorySize, SMEM_TOTAL);
        attr_done = true;
    }

    prep1_kernel<<<KK, 256>>>(M);
    int nb = (N + MROWS - 1) / MROWS;
    main_mma_kernel<<<nb, 512, SMEM_TOTAL>>>(X, pi, (float*)d_out, N, nb);
}